// round 1
// baseline (speedup 1.0000x reference)
#include <cuda_runtime.h>
#include <math.h>

#define BB 16
#define SS 1024
#define NIN 7
#define NHID 28
#define HEADS 7
#define HD 4

// Scratch (device globals — no allocation allowed)
__device__ float g_Q [BB*HEADS*SS*HD];
__device__ float g_K [BB*HEADS*SS*HD];
__device__ float g_V [BB*HEADS*SS*HD];
__device__ float g_AO[BB*SS*NHID];
__device__ float g_Q2[BB*SS*NHID];
__device__ float g_K2[BB*SS*NHID];

// ---------------------------------------------------------------------------
// K1: QKV projection. 1 thread per (b,s) row. Q/K/V stored [B,H,S,4] (float4).
// ---------------------------------------------------------------------------
__global__ void k_qkv(const float* __restrict__ x,
                      const float* __restrict__ Wq, const float* __restrict__ bq,
                      const float* __restrict__ Wk, const float* __restrict__ bk,
                      const float* __restrict__ Wv, const float* __restrict__ bv) {
    __shared__ float sw[672]; // Wq[0..195] bq[196..223] Wk[224..419] bk[420..447] Wv[448..643] bv[644..671]
    int tid = threadIdx.x;
    for (int i = tid; i < 196; i += blockDim.x) {
        sw[i] = Wq[i]; sw[224 + i] = Wk[i]; sw[448 + i] = Wv[i];
    }
    if (tid < 28) { sw[196 + tid] = bq[tid]; sw[420 + tid] = bk[tid]; sw[644 + tid] = bv[tid]; }
    __syncthreads();

    int r = blockIdx.x * blockDim.x + tid;        // 0..16383
    int b = r >> 10, s = r & 1023;

    float xv[7];
#pragma unroll
    for (int i = 0; i < 7; i++) xv[i] = x[r * 7 + i];

#pragma unroll
    for (int h = 0; h < 7; h++) {
        float qa[4], ka[4], va[4];
#pragma unroll
        for (int d = 0; d < 4; d++) {
            int j = h * 4 + d;
            float aq = sw[196 + j], ak = sw[420 + j], av = sw[644 + j];
#pragma unroll
            for (int i = 0; i < 7; i++) {
                float xi = xv[i];
                aq += xi * sw[i * 28 + j];
                ak += xi * sw[224 + i * 28 + j];
                av += xi * sw[448 + i * 28 + j];
            }
            qa[d] = aq; ka[d] = ak; va[d] = av;
        }
        int o = (b * 7 + h) * 1024 + s;
        reinterpret_cast<float4*>(g_Q)[o] = make_float4(qa[0], qa[1], qa[2], qa[3]);
        reinterpret_cast<float4*>(g_K)[o] = make_float4(ka[0], ka[1], ka[2], ka[3]);
        reinterpret_cast<float4*>(g_V)[o] = make_float4(va[0], va[1], va[2], va[3]);
    }
}

// ---------------------------------------------------------------------------
// K2: first attention. Block = (qchunk, h, b); K_h, V_h resident in SMEM.
// 1 q per thread. Softmax without max subtraction (scores bounded ~6 nats).
// Q pre-scaled by 0.5*log2(e) so exp2f is the whole exponent path.
// ---------------------------------------------------------------------------
__global__ void __launch_bounds__(256) k_attn1() {
    __shared__ float4 Ksh[1024];
    __shared__ float4 Vsh[1024];
    int b = blockIdx.z, h = blockIdx.y, chunk = blockIdx.x;
    int bh = b * 7 + h;
    const float4* Kg = reinterpret_cast<const float4*>(g_K) + bh * 1024;
    const float4* Vg = reinterpret_cast<const float4*>(g_V) + bh * 1024;
    for (int t = threadIdx.x; t < 1024; t += 256) { Ksh[t] = Kg[t]; Vsh[t] = Vg[t]; }
    __syncthreads();

    int q = chunk * 256 + threadIdx.x;
    float4 qv = reinterpret_cast<const float4*>(g_Q)[bh * 1024 + q];
    const float c = 0.5f * 1.4426950408889634f;   // fold 1/sqrt(4) and log2(e)
    qv.x *= c; qv.y *= c; qv.z *= c; qv.w *= c;

    float l = 0.f, a0 = 0.f, a1 = 0.f, a2 = 0.f, a3 = 0.f;
#pragma unroll 4
    for (int k = 0; k < 1024; k++) {
        float4 kk = Ksh[k];
        float sc = qv.x * kk.x + qv.y * kk.y + qv.z * kk.z + qv.w * kk.w;
        float p = exp2f(sc);
        float4 vv = Vsh[k];
        l += p;
        a0 += p * vv.x; a1 += p * vv.y; a2 += p * vv.z; a3 += p * vv.w;
    }
    float inv = 1.f / l;
    float4 o = make_float4(a0 * inv, a1 * inv, a2 * inv, a3 * inv);
    // AO[b][q][h*4 + d]  — offset is multiple of 4 floats -> float4-aligned
    *reinterpret_cast<float4*>(g_AO + ((b * 1024 + q) * 28 + h * 4)) = o;
}

// ---------------------------------------------------------------------------
// K3: LayerNorm(28) + FFN(28->7) + ReLU + residual -> out7 (d_out head),
// then Q2/K2 projections (7->28) into scratch. 1 thread per row.
// ---------------------------------------------------------------------------
__global__ void k_lnffn(const float* __restrict__ x,
                        const float* __restrict__ lnw, const float* __restrict__ lnb,
                        const float* __restrict__ W1,  const float* __restrict__ b1,
                        const float* __restrict__ Wq2, const float* __restrict__ bq2,
                        const float* __restrict__ Wk2, const float* __restrict__ bk2,
                        float* __restrict__ out7) {
    __shared__ float s_lnw[28], s_lnb[28], s_W1[196], s_b1[7];
    __shared__ float s_Wq2[196], s_bq2[28], s_Wk2[196], s_bk2[28];
    int tid = threadIdx.x;
    for (int i = tid; i < 196; i += blockDim.x) { s_W1[i] = W1[i]; s_Wq2[i] = Wq2[i]; s_Wk2[i] = Wk2[i]; }
    if (tid < 28) { s_lnw[tid] = lnw[tid]; s_lnb[tid] = lnb[tid]; s_bq2[tid] = bq2[tid]; s_bk2[tid] = bk2[tid]; }
    if (tid < 7)  { s_b1[tid] = b1[tid]; }
    __syncthreads();

    int r = blockIdx.x * blockDim.x + tid;
    float a[28];
    const float4* ap = reinterpret_cast<const float4*>(g_AO + r * 28);
#pragma unroll
    for (int i = 0; i < 7; i++) {
        float4 t = ap[i];
        a[4*i] = t.x; a[4*i+1] = t.y; a[4*i+2] = t.z; a[4*i+3] = t.w;
    }
    float mu = 0.f;
#pragma unroll
    for (int j = 0; j < 28; j++) mu += a[j];
    mu *= (1.f / 28.f);
    float var = 0.f;
#pragma unroll
    for (int j = 0; j < 28; j++) { float d = a[j] - mu; var += d * d; }
    var *= (1.f / 28.f);
    float rs = rsqrtf(var + 1e-5f);

    float y[28];
#pragma unroll
    for (int j = 0; j < 28; j++) y[j] = (a[j] - mu) * rs * s_lnw[j] + s_lnb[j];

    float z[7];
#pragma unroll
    for (int i = 0; i < 7; i++) {
        float t = s_b1[i];
#pragma unroll
        for (int j = 0; j < 28; j++) t += y[j] * s_W1[j * 7 + i];
        t = fmaxf(t, 0.f) + x[r * 7 + i];
        z[i] = t;
        out7[r * 7 + i] = t;
    }
#pragma unroll
    for (int j = 0; j < 28; j++) {
        float tq = s_bq2[j], tk = s_bk2[j];
#pragma unroll
        for (int i = 0; i < 7; i++) {
            tq += z[i] * s_Wq2[i * 28 + j];
            tk += z[i] * s_Wk2[i * 28 + j];
        }
        g_Q2[r * 28 + j] = tq;
        g_K2[r * 28 + j] = tk;
    }
}

// ---------------------------------------------------------------------------
// K4: second attention weights. K2[b] (1024x28 = 112KB) in dynamic SMEM.
// 8 warps/block, each warp processes 2 q rows at a time (shares every K2 LDS
// across 2 dot products -> halves SMEM traffic vs FMA). 112B rows keep
// LDS.128 conflict-free (lane stride 28 words).
// ---------------------------------------------------------------------------
__global__ void __launch_bounds__(256, 1) k_attn2(float* __restrict__ out) {
    extern __shared__ float K2s[];                 // 1024*28 floats
    int b = blockIdx.y, tile = blockIdx.x;         // 32 tiles of 32 q rows
    const float4* src = reinterpret_cast<const float4*>(g_K2 + b * SS * 28);
    float4* dst = reinterpret_cast<float4*>(K2s);
    for (int t = threadIdx.x; t < 1024 * 7; t += 256) dst[t] = src[t];
    __syncthreads();

    int warp = threadIdx.x >> 5, lane = threadIdx.x & 31;
    const float SC2 = 1.4426950408889634f / 2.6457513110645906f; // log2(e)/sqrt(7)

#pragma unroll 1
    for (int rep = 0; rep < 2; rep++) {
        int qa = tile * 32 + warp * 4 + rep * 2;
        int qb = qa + 1;

        float Qa[28], Qb[28];
        const float4* qap = reinterpret_cast<const float4*>(g_Q2 + (b * 1024 + qa) * 28);
        const float4* qbp = reinterpret_cast<const float4*>(g_Q2 + (b * 1024 + qb) * 28);
#pragma unroll
        for (int i = 0; i < 7; i++) {
            float4 t = qap[i];
            Qa[4*i] = t.x * SC2; Qa[4*i+1] = t.y * SC2; Qa[4*i+2] = t.z * SC2; Qa[4*i+3] = t.w * SC2;
            float4 u = qbp[i];
            Qb[4*i] = u.x * SC2; Qb[4*i+1] = u.y * SC2; Qb[4*i+2] = u.z * SC2; Qb[4*i+3] = u.w * SC2;
        }

        float sA[32], sB[32];
        float mA = -1e30f, mB = -1e30f;
#pragma unroll
        for (int i = 0; i < 32; i++) {
            const float4* kr = reinterpret_cast<const float4*>(&K2s[(i * 32 + lane) * 28]);
            float a0 = 0.f, a1 = 0.f, b0 = 0.f, b1 = 0.f;
#pragma unroll
            for (int d = 0; d < 7; d++) {
                float4 kk = kr[d];
                a0 += Qa[4*d]   * kk.x + Qa[4*d+2] * kk.z;
                a1 += Qa[4*d+1] * kk.y + Qa[4*d+3] * kk.w;
                b0 += Qb[4*d]   * kk.x + Qb[4*d+2] * kk.z;
                b1 += Qb[4*d+1] * kk.y + Qb[4*d+3] * kk.w;
            }
            float sa = a0 + a1, sb = b0 + b1;
            sA[i] = sa; sB[i] = sb;
            mA = fmaxf(mA, sa); mB = fmaxf(mB, sb);
        }
#pragma unroll
        for (int o = 16; o > 0; o >>= 1) {
            mA = fmaxf(mA, __shfl_xor_sync(0xffffffffu, mA, o));
            mB = fmaxf(mB, __shfl_xor_sync(0xffffffffu, mB, o));
        }
        float suA = 0.f, suB = 0.f;
#pragma unroll
        for (int i = 0; i < 32; i++) {
            sA[i] = exp2f(sA[i] - mA); suA += sA[i];
            sB[i] = exp2f(sB[i] - mB); suB += sB[i];
        }
#pragma unroll
        for (int o = 16; o > 0; o >>= 1) {
            suA += __shfl_xor_sync(0xffffffffu, suA, o);
            suB += __shfl_xor_sync(0xffffffffu, suB, o);
        }
        float ivA = 1.f / suA, ivB = 1.f / suB;

        float* oA = out + (size_t)(b * 1024 + qa) * 1024 + lane;
        float* oB = oA + 1024;
#pragma unroll
        for (int i = 0; i < 32; i++) {
            oA[i * 32] = sA[i] * ivA;
            oB[i * 32] = sB[i] * ivB;
        }
    }
}

// ---------------------------------------------------------------------------
extern "C" void kernel_launch(void* const* d_in, const int* in_sizes, int n_in,
                              void* d_out, int out_size) {
    const float* x    = (const float*)d_in[0];
    const float* Wq   = (const float*)d_in[1];
    const float* bq   = (const float*)d_in[2];
    const float* Wk   = (const float*)d_in[3];
    const float* bk   = (const float*)d_in[4];
    const float* Wv   = (const float*)d_in[5];
    const float* bv   = (const float*)d_in[6];
    const float* lnw  = (const float*)d_in[7];
    const float* lnb  = (const float*)d_in[8];
    const float* W1   = (const float*)d_in[9];
    const float* b1   = (const float*)d_in[10];
    const float* Wq2  = (const float*)d_in[11];
    const float* bq2  = (const float*)d_in[12];
    const float* Wk2  = (const float*)d_in[13];
    const float* bk2  = (const float*)d_in[14];
    float* out = (float*)d_out;

    static_assert(BB * SS * NIN == 114688, "out head size");

    cudaFuncSetAttribute(k_attn2, cudaFuncAttributeMaxDynamicSharedMemorySize,
                         1024 * 28 * sizeof(float));

    k_qkv<<<128, 128>>>(x, Wq, bq, Wk, bk, Wv, bv);
    k_attn1<<<dim3(4, 7, 16), 256>>>();
    k_lnffn<<<128, 128>>>(x, lnw, lnb, W1, b1, Wq2, bq2, Wk2, bk2, out);
    k_attn2<<<dim3(32, 16), 256, 1024 * 28 * sizeof(float)>>>(out + BB * SS * NIN);
}

// round 3
// speedup vs baseline: 2.0079x; 2.0079x over previous
#include <cuda_runtime.h>
#include <math.h>

#define BB 16
#define SS 1024
#define NIN 7
#define NHID 28
#define HEADS 7
#define HD 4

// Scratch (device globals — no allocation allowed)
__device__ float g_Q [BB*HEADS*SS*HD];
__device__ float g_K [BB*HEADS*SS*HD];
__device__ float g_V [BB*HEADS*SS*HD];
__device__ float g_AO[BB*SS*NHID];
__device__ float g_Q2[BB*SS*NHID];
__device__ float g_K2[BB*SS*NHID];

// ---------------------------------------------------------------------------
// helpers
// ---------------------------------------------------------------------------
typedef unsigned long long u64;
__device__ __forceinline__ float ex2(float x) {            // single MUFU.EX2
    float r; asm("ex2.approx.ftz.f32 %0, %1;" : "=f"(r) : "f"(x)); return r;
}
__device__ __forceinline__ u64 pk2(float a, float b) {
    u64 r; asm("mov.b64 %0, {%1,%2};" : "=l"(r) : "f"(a), "f"(b)); return r;
}
__device__ __forceinline__ void up2(u64 v, float& a, float& b) {
    asm("mov.b64 {%0,%1}, %2;" : "=f"(a), "=f"(b) : "l"(v));
}
__device__ __forceinline__ u64 f2fma(u64 a, u64 b, u64 c) {
    u64 d; asm("fma.rn.f32x2 %0, %1, %2, %3;" : "=l"(d) : "l"(a), "l"(b), "l"(c)); return d;
}
__device__ __forceinline__ u64 f2mul(u64 a, u64 b) {
    u64 d; asm("mul.rn.f32x2 %0, %1, %2;" : "=l"(d) : "l"(a), "l"(b)); return d;
}
__device__ __forceinline__ u64 f2add(u64 a, u64 b) {
    u64 d; asm("add.rn.f32x2 %0, %1, %2;" : "=l"(d) : "l"(a), "l"(b)); return d;
}

// ---------------------------------------------------------------------------
// K1: QKV projection. 1 thread per (b,s) row. Q/K/V stored [B,H,S,4] (float4).
// ---------------------------------------------------------------------------
__global__ void k_qkv(const float* __restrict__ x,
                      const float* __restrict__ Wq, const float* __restrict__ bq,
                      const float* __restrict__ Wk, const float* __restrict__ bk,
                      const float* __restrict__ Wv, const float* __restrict__ bv) {
    __shared__ float sw[672];
    int tid = threadIdx.x;
    for (int i = tid; i < 196; i += blockDim.x) {
        sw[i] = Wq[i]; sw[224 + i] = Wk[i]; sw[448 + i] = Wv[i];
    }
    if (tid < 28) { sw[196 + tid] = bq[tid]; sw[420 + tid] = bk[tid]; sw[644 + tid] = bv[tid]; }
    __syncthreads();

    int r = blockIdx.x * blockDim.x + tid;        // 0..16383
    int b = r >> 10, s = r & 1023;

    float xv[7];
#pragma unroll
    for (int i = 0; i < 7; i++) xv[i] = x[r * 7 + i];

#pragma unroll
    for (int h = 0; h < 7; h++) {
        float qa[4], ka[4], va[4];
#pragma unroll
        for (int d = 0; d < 4; d++) {
            int j = h * 4 + d;
            float aq = sw[196 + j], ak = sw[420 + j], av = sw[644 + j];
#pragma unroll
            for (int i = 0; i < 7; i++) {
                float xi = xv[i];
                aq += xi * sw[i * 28 + j];
                ak += xi * sw[224 + i * 28 + j];
                av += xi * sw[448 + i * 28 + j];
            }
            qa[d] = aq; ka[d] = ak; va[d] = av;
        }
        int o = (b * 7 + h) * 1024 + s;
        reinterpret_cast<float4*>(g_Q)[o] = make_float4(qa[0], qa[1], qa[2], qa[3]);
        reinterpret_cast<float4*>(g_K)[o] = make_float4(ka[0], ka[1], ka[2], ka[3]);
        reinterpret_cast<float4*>(g_V)[o] = make_float4(va[0], va[1], va[2], va[3]);
    }
}

// ---------------------------------------------------------------------------
// K2: first attention, f32x2 packed over q-pairs.
// Each thread handles 2 q rows (q, q+256). K/V in smem pre-duplicated (k,k)
// so every packed FMA serves both rows: 9 f32x2 ops per (2q, k) vs 18 FFMA.
// Softmax max-free (scores bounded), ex2.approx single-MUFU.
// smem: 64KB dynamic (Kdup 32KB + Vdup 32KB) -> 3 CTA/SM.
// ---------------------------------------------------------------------------
__global__ void __launch_bounds__(256) k_attn1() {
    extern __shared__ ulonglong2 s1[];           // [0,2048): Kdup, [2048,4096): Vdup
    ulonglong2* Ks = s1;
    ulonglong2* Vs = s1 + 2048;
    int b = blockIdx.z, h = blockIdx.y, chunk = blockIdx.x;
    int bh = b * 7 + h;
    const float4* Kg = reinterpret_cast<const float4*>(g_K) + bh * 1024;
    const float4* Vg = reinterpret_cast<const float4*>(g_V) + bh * 1024;
    for (int t = threadIdx.x; t < 1024; t += 256) {
        float4 kk = Kg[t];
        Ks[2*t]   = make_ulonglong2(pk2(kk.x, kk.x), pk2(kk.y, kk.y));
        Ks[2*t+1] = make_ulonglong2(pk2(kk.z, kk.z), pk2(kk.w, kk.w));
        float4 vv = Vg[t];
        Vs[2*t]   = make_ulonglong2(pk2(vv.x, vv.x), pk2(vv.y, vv.y));
        Vs[2*t+1] = make_ulonglong2(pk2(vv.z, vv.z), pk2(vv.w, vv.w));
    }
    __syncthreads();

    int qA = chunk * 512 + threadIdx.x;          // chunk in {0,1}
    int qB = qA + 256;
    float4 qa = reinterpret_cast<const float4*>(g_Q)[bh * 1024 + qA];
    float4 qb = reinterpret_cast<const float4*>(g_Q)[bh * 1024 + qB];
    const float c = 0.5f * 1.4426950408889634f;  // 1/sqrt(4) * log2(e)
    u64 qp0 = pk2(qa.x * c, qb.x * c);
    u64 qp1 = pk2(qa.y * c, qb.y * c);
    u64 qp2 = pk2(qa.z * c, qb.z * c);
    u64 qp3 = pk2(qa.w * c, qb.w * c);

    u64 acc0 = 0ull, acc1 = 0ull, acc2 = 0ull, acc3 = 0ull, l2 = 0ull;
#pragma unroll 4
    for (int k = 0; k < 1024; k++) {
        ulonglong2 k01 = Ks[2*k];
        ulonglong2 k23 = Ks[2*k+1];
        u64 s2 = f2mul(qp0, k01.x);
        s2 = f2fma(qp1, k01.y, s2);
        s2 = f2fma(qp2, k23.x, s2);
        s2 = f2fma(qp3, k23.y, s2);
        float sa, sb; up2(s2, sa, sb);
        float pa = ex2(sa), pb = ex2(sb);
        u64 p2 = pk2(pa, pb);
        ulonglong2 v01 = Vs[2*k];
        ulonglong2 v23 = Vs[2*k+1];
        acc0 = f2fma(p2, v01.x, acc0);
        acc1 = f2fma(p2, v01.y, acc1);
        acc2 = f2fma(p2, v23.x, acc2);
        acc3 = f2fma(p2, v23.y, acc3);
        l2 = f2add(l2, p2);
    }
    float lA, lB; up2(l2, lA, lB);
    float iA = 1.f / lA, iB = 1.f / lB;
    float a0,b0,a1,b1,a2,b2,a3,b3;
    up2(acc0, a0, b0); up2(acc1, a1, b1); up2(acc2, a2, b2); up2(acc3, a3, b3);
    *reinterpret_cast<float4*>(g_AO + ((b * 1024 + qA) * 28 + h * 4)) =
        make_float4(a0 * iA, a1 * iA, a2 * iA, a3 * iA);
    *reinterpret_cast<float4*>(g_AO + ((b * 1024 + qB) * 28 + h * 4)) =
        make_float4(b0 * iB, b1 * iB, b2 * iB, b3 * iB);
}

// ---------------------------------------------------------------------------
// K3: LayerNorm(28) + FFN(28->7) + ReLU + residual -> out7 (d_out head),
// then Q2/K2 projections (7->28) into scratch. 1 thread per row.
// ---------------------------------------------------------------------------
__global__ void k_lnffn(const float* __restrict__ x,
                        const float* __restrict__ lnw, const float* __restrict__ lnb,
                        const float* __restrict__ W1,  const float* __restrict__ b1,
                        const float* __restrict__ Wq2, const float* __restrict__ bq2,
                        const float* __restrict__ Wk2, const float* __restrict__ bk2,
                        float* __restrict__ out7) {
    __shared__ float s_lnw[28], s_lnb[28], s_W1[196], s_b1[7];
    __shared__ float s_Wq2[196], s_bq2[28], s_Wk2[196], s_bk2[28];
    int tid = threadIdx.x;
    for (int i = tid; i < 196; i += blockDim.x) { s_W1[i] = W1[i]; s_Wq2[i] = Wq2[i]; s_Wk2[i] = Wk2[i]; }
    if (tid < 28) { s_lnw[tid] = lnw[tid]; s_lnb[tid] = lnb[tid]; s_bq2[tid] = bq2[tid]; s_bk2[tid] = bk2[tid]; }
    if (tid < 7)  { s_b1[tid] = b1[tid]; }
    __syncthreads();

    int r = blockIdx.x * blockDim.x + tid;
    float a[28];
    const float4* ap = reinterpret_cast<const float4*>(g_AO + r * 28);
#pragma unroll
    for (int i = 0; i < 7; i++) {
        float4 t = ap[i];
        a[4*i] = t.x; a[4*i+1] = t.y; a[4*i+2] = t.z; a[4*i+3] = t.w;
    }
    float mu = 0.f;
#pragma unroll
    for (int j = 0; j < 28; j++) mu += a[j];
    mu *= (1.f / 28.f);
    float var = 0.f;
#pragma unroll
    for (int j = 0; j < 28; j++) { float d = a[j] - mu; var += d * d; }
    var *= (1.f / 28.f);
    float rs = rsqrtf(var + 1e-5f);

    float y[28];
#pragma unroll
    for (int j = 0; j < 28; j++) y[j] = (a[j] - mu) * rs * s_lnw[j] + s_lnb[j];

    float z[7];
#pragma unroll
    for (int i = 0; i < 7; i++) {
        float t = s_b1[i];
#pragma unroll
        for (int j = 0; j < 28; j++) t += y[j] * s_W1[j * 7 + i];
        t = fmaxf(t, 0.f) + x[r * 7 + i];
        z[i] = t;
        out7[r * 7 + i] = t;
    }
#pragma unroll
    for (int j = 0; j < 28; j++) {
        float tq = s_bq2[j], tk = s_bk2[j];
#pragma unroll
        for (int i = 0; i < 7; i++) {
            tq += z[i] * s_Wq2[i * 28 + j];
            tk += z[i] * s_Wk2[i * 28 + j];
        }
        g_Q2[r * 28 + j] = tq;
        g_K2[r * 28 + j] = tk;
    }
}

// ---------------------------------------------------------------------------
// K4: second attention weights. K2[b] (1024x28 = 112KB) in dynamic SMEM.
// No score registers: max-free softmax streams p=exp2(s) to gmem while
// accumulating row sums, then re-reads (L2-hit) and scales by 1/sum.
// Low regs -> __launch_bounds__(256,2) -> 2 CTAs/SM (224KB smem), 16 warps/SM.
// ---------------------------------------------------------------------------
__global__ void __launch_bounds__(256, 2) k_attn2(float* __restrict__ out) {
    extern __shared__ float K2s[];                 // 1024*28 floats
    int b = blockIdx.y, tile = blockIdx.x;         // 32 tiles of 32 q rows
    const float4* src = reinterpret_cast<const float4*>(g_K2 + b * SS * 28);
    float4* dst = reinterpret_cast<float4*>(K2s);
    for (int t = threadIdx.x; t < 1024 * 7; t += 256) dst[t] = src[t];
    __syncthreads();

    int warp = threadIdx.x >> 5, lane = threadIdx.x & 31;
    const float SC2 = 1.4426950408889634f / 2.6457513110645906f; // log2(e)/sqrt(7)

#pragma unroll 1
    for (int rep = 0; rep < 2; rep++) {
        int qa = tile * 32 + warp * 4 + rep * 2;
        int qb = qa + 1;

        float Qa[28], Qb[28];
        const float4* qap = reinterpret_cast<const float4*>(g_Q2 + (b * 1024 + qa) * 28);
        const float4* qbp = reinterpret_cast<const float4*>(g_Q2 + (b * 1024 + qb) * 28);
#pragma unroll
        for (int i = 0; i < 7; i++) {
            float4 t = qap[i];
            Qa[4*i] = t.x * SC2; Qa[4*i+1] = t.y * SC2; Qa[4*i+2] = t.z * SC2; Qa[4*i+3] = t.w * SC2;
            float4 u = qbp[i];
            Qb[4*i] = u.x * SC2; Qb[4*i+1] = u.y * SC2; Qb[4*i+2] = u.z * SC2; Qb[4*i+3] = u.w * SC2;
        }

        float* oA = out + (b * 1024 + qa) * 1024;
        float* oB = oA + 1024;
        float suA = 0.f, suB = 0.f;
#pragma unroll 4
        for (int i = 0; i < 32; i++) {
            int k = i * 32 + lane;
            const float4* kr = reinterpret_cast<const float4*>(&K2s[k * 28]);
            float a0 = 0.f, a1 = 0.f, b0 = 0.f, b1 = 0.f;
#pragma unroll
            for (int d = 0; d < 7; d++) {
                float4 kk = kr[d];
                a0 += Qa[4*d]   * kk.x + Qa[4*d+2] * kk.z;
                a1 += Qa[4*d+1] * kk.y + Qa[4*d+3] * kk.w;
                b0 += Qb[4*d]   * kk.x + Qb[4*d+2] * kk.z;
                b1 += Qb[4*d+1] * kk.y + Qb[4*d+3] * kk.w;
            }
            float pa = ex2(a0 + a1);
            float pb = ex2(b0 + b1);
            suA += pa; suB += pb;
            oA[k] = pa;
            oB[k] = pb;
        }
#pragma unroll
        for (int o = 16; o > 0; o >>= 1) {
            suA += __shfl_xor_sync(0xffffffffu, suA, o);
            suB += __shfl_xor_sync(0xffffffffu, suB, o);
        }
        float ivA = 1.f / suA, ivB = 1.f / suB;

        // readback (L2-resident) + normalize
#pragma unroll 4
        for (int i = 0; i < 32; i++) {
            int k = i * 32 + lane;
            oA[k] *= ivA;
            oB[k] *= ivB;
        }
    }
}

// ---------------------------------------------------------------------------
extern "C" void kernel_launch(void* const* d_in, const int* in_sizes, int n_in,
                              void* d_out, int out_size) {
    const float* x    = (const float*)d_in[0];
    const float* Wq   = (const float*)d_in[1];
    const float* bq   = (const float*)d_in[2];
    const float* Wk   = (const float*)d_in[3];
    const float* bk   = (const float*)d_in[4];
    const float* Wv   = (const float*)d_in[5];
    const float* bv   = (const float*)d_in[6];
    const float* lnw  = (const float*)d_in[7];
    const float* lnb  = (const float*)d_in[8];
    const float* W1   = (const float*)d_in[9];
    const float* b1   = (const float*)d_in[10];
    const float* Wq2  = (const float*)d_in[11];
    const float* bq2  = (const float*)d_in[12];
    const float* Wk2  = (const float*)d_in[13];
    const float* bk2  = (const float*)d_in[14];
    float* out = (float*)d_out;

    cudaFuncSetAttribute(k_attn1, cudaFuncAttributeMaxDynamicSharedMemorySize, 65536);
    cudaFuncSetAttribute(k_attn2, cudaFuncAttributeMaxDynamicSharedMemorySize,
                         1024 * 28 * sizeof(float));

    k_qkv<<<128, 128>>>(x, Wq, bq, Wk, bk, Wv, bv);
    k_attn1<<<dim3(2, 7, 16), 256, 65536>>>();
    k_lnffn<<<128, 128>>>(x, lnw, lnb, W1, b1, Wq2, bq2, Wk2, bk2, out);
    k_attn2<<<dim3(32, 16), 256, 1024 * 28 * sizeof(float)>>>(out + BB * SS * NIN);
}

// round 4
// speedup vs baseline: 2.0814x; 1.0366x over previous
#include <cuda_runtime.h>
#include <math.h>

#define BB 16
#define SS 1024
#define NIN 7
#define NHID 28
#define HEADS 7
#define HD 4

// Scratch (device globals — no allocation allowed)
__device__ float g_Q [BB*HEADS*SS*HD];
__device__ float g_K [BB*HEADS*SS*HD];
__device__ float g_V [BB*HEADS*SS*HD];
__device__ float g_AO[BB*SS*NHID];
__device__ float g_Q2[BB*SS*NHID];
__device__ float g_K2[BB*SS*NHID];

// ---------------------------------------------------------------------------
// helpers
// ---------------------------------------------------------------------------
typedef unsigned long long u64;
__device__ __forceinline__ float ex2(float x) {            // single MUFU.EX2
    float r; asm("ex2.approx.ftz.f32 %0, %1;" : "=f"(r) : "f"(x)); return r;
}
__device__ __forceinline__ u64 pk2(float a, float b) {
    u64 r; asm("mov.b64 %0, {%1,%2};" : "=l"(r) : "f"(a), "f"(b)); return r;
}
__device__ __forceinline__ void up2(u64 v, float& a, float& b) {
    asm("mov.b64 {%0,%1}, %2;" : "=f"(a), "=f"(b) : "l"(v));
}
__device__ __forceinline__ u64 f2fma(u64 a, u64 b, u64 c) {
    u64 d; asm("fma.rn.f32x2 %0, %1, %2, %3;" : "=l"(d) : "l"(a), "l"(b), "l"(c)); return d;
}
__device__ __forceinline__ u64 f2mul(u64 a, u64 b) {
    u64 d; asm("mul.rn.f32x2 %0, %1, %2;" : "=l"(d) : "l"(a), "l"(b)); return d;
}
__device__ __forceinline__ u64 f2add(u64 a, u64 b) {
    u64 d; asm("add.rn.f32x2 %0, %1, %2;" : "=l"(d) : "l"(a), "l"(b)); return d;
}

// ---------------------------------------------------------------------------
// K1: QKV projection. 1 thread per (b,s) row. Q/K/V stored [B,H,S,4] (float4).
// ---------------------------------------------------------------------------
__global__ void k_qkv(const float* __restrict__ x,
                      const float* __restrict__ Wq, const float* __restrict__ bq,
                      const float* __restrict__ Wk, const float* __restrict__ bk,
                      const float* __restrict__ Wv, const float* __restrict__ bv) {
    __shared__ float sw[672];
    int tid = threadIdx.x;
    for (int i = tid; i < 196; i += blockDim.x) {
        sw[i] = Wq[i]; sw[224 + i] = Wk[i]; sw[448 + i] = Wv[i];
    }
    if (tid < 28) { sw[196 + tid] = bq[tid]; sw[420 + tid] = bk[tid]; sw[644 + tid] = bv[tid]; }
    __syncthreads();

    int r = blockIdx.x * blockDim.x + tid;        // 0..16383
    int b = r >> 10, s = r & 1023;

    float xv[7];
#pragma unroll
    for (int i = 0; i < 7; i++) xv[i] = x[r * 7 + i];

#pragma unroll
    for (int h = 0; h < 7; h++) {
        float qa[4], ka[4], va[4];
#pragma unroll
        for (int d = 0; d < 4; d++) {
            int j = h * 4 + d;
            float aq = sw[196 + j], ak = sw[420 + j], av = sw[644 + j];
#pragma unroll
            for (int i = 0; i < 7; i++) {
                float xi = xv[i];
                aq += xi * sw[i * 28 + j];
                ak += xi * sw[224 + i * 28 + j];
                av += xi * sw[448 + i * 28 + j];
            }
            qa[d] = aq; ka[d] = ak; va[d] = av;
        }
        int o = (b * 7 + h) * 1024 + s;
        reinterpret_cast<float4*>(g_Q)[o] = make_float4(qa[0], qa[1], qa[2], qa[3]);
        reinterpret_cast<float4*>(g_K)[o] = make_float4(ka[0], ka[1], ka[2], ka[3]);
        reinterpret_cast<float4*>(g_V)[o] = make_float4(va[0], va[1], va[2], va[3]);
    }
}

// ---------------------------------------------------------------------------
// K2: first attention. 4 q rows per thread as two f32x2 row-pairs; K/V
// duplicated (k,k) in smem so each uniform (broadcast) LDS serves all 4 rows.
// Max-free softmax, ex2.approx. smem 64KB -> 3 CTA/SM at 128 threads.
// ---------------------------------------------------------------------------
__global__ void __launch_bounds__(128) k_attn1() {
    extern __shared__ ulonglong2 s1[];           // [0,2048): Kdup, [2048,4096): Vdup
    ulonglong2* Ks = s1;
    ulonglong2* Vs = s1 + 2048;
    int b = blockIdx.z, h = blockIdx.y, chunk = blockIdx.x;
    int bh = b * 7 + h;
    const float4* Kg = reinterpret_cast<const float4*>(g_K) + bh * 1024;
    const float4* Vg = reinterpret_cast<const float4*>(g_V) + bh * 1024;
    for (int t = threadIdx.x; t < 1024; t += 128) {
        float4 kk = Kg[t];
        Ks[2*t]   = make_ulonglong2(pk2(kk.x, kk.x), pk2(kk.y, kk.y));
        Ks[2*t+1] = make_ulonglong2(pk2(kk.z, kk.z), pk2(kk.w, kk.w));
        float4 vv = Vg[t];
        Vs[2*t]   = make_ulonglong2(pk2(vv.x, vv.x), pk2(vv.y, vv.y));
        Vs[2*t+1] = make_ulonglong2(pk2(vv.z, vv.z), pk2(vv.w, vv.w));
    }
    __syncthreads();

    int qA = chunk * 512 + threadIdx.x;          // chunk in {0,1}; rows +0,128,256,384
    const float c = 0.5f * 1.4426950408889634f;  // 1/sqrt(4) * log2(e)
    float4 qa = reinterpret_cast<const float4*>(g_Q)[bh * 1024 + qA];
    float4 qb = reinterpret_cast<const float4*>(g_Q)[bh * 1024 + qA + 128];
    float4 qc = reinterpret_cast<const float4*>(g_Q)[bh * 1024 + qA + 256];
    float4 qd = reinterpret_cast<const float4*>(g_Q)[bh * 1024 + qA + 384];
    u64 qab0 = pk2(qa.x * c, qb.x * c), qab1 = pk2(qa.y * c, qb.y * c);
    u64 qab2 = pk2(qa.z * c, qb.z * c), qab3 = pk2(qa.w * c, qb.w * c);
    u64 qcd0 = pk2(qc.x * c, qd.x * c), qcd1 = pk2(qc.y * c, qd.y * c);
    u64 qcd2 = pk2(qc.z * c, qd.z * c), qcd3 = pk2(qc.w * c, qd.w * c);

    u64 aab0 = 0ull, aab1 = 0ull, aab2 = 0ull, aab3 = 0ull, lab = 0ull;
    u64 acd0 = 0ull, acd1 = 0ull, acd2 = 0ull, acd3 = 0ull, lcd = 0ull;
#pragma unroll 4
    for (int k = 0; k < 1024; k++) {
        ulonglong2 k01 = Ks[2*k];
        ulonglong2 k23 = Ks[2*k+1];
        u64 sab = f2mul(qab0, k01.x);
        u64 scd = f2mul(qcd0, k01.x);
        sab = f2fma(qab1, k01.y, sab);  scd = f2fma(qcd1, k01.y, scd);
        sab = f2fma(qab2, k23.x, sab);  scd = f2fma(qcd2, k23.x, scd);
        sab = f2fma(qab3, k23.y, sab);  scd = f2fma(qcd3, k23.y, scd);
        float sa, sb, sc, sd;
        up2(sab, sa, sb); up2(scd, sc, sd);
        u64 pab = pk2(ex2(sa), ex2(sb));
        u64 pcd = pk2(ex2(sc), ex2(sd));
        ulonglong2 v01 = Vs[2*k];
        ulonglong2 v23 = Vs[2*k+1];
        aab0 = f2fma(pab, v01.x, aab0);  acd0 = f2fma(pcd, v01.x, acd0);
        aab1 = f2fma(pab, v01.y, aab1);  acd1 = f2fma(pcd, v01.y, acd1);
        aab2 = f2fma(pab, v23.x, aab2);  acd2 = f2fma(pcd, v23.x, acd2);
        aab3 = f2fma(pab, v23.y, aab3);  acd3 = f2fma(pcd, v23.y, acd3);
        lab = f2add(lab, pab);           lcd = f2add(lcd, pcd);
    }
    float lA, lB, lC, lD;
    up2(lab, lA, lB); up2(lcd, lC, lD);
    float iA = 1.f / lA, iB = 1.f / lB, iC = 1.f / lC, iD = 1.f / lD;
    float x0, y0, x1, y1, x2, y2, x3, y3;
    up2(aab0, x0, y0); up2(aab1, x1, y1); up2(aab2, x2, y2); up2(aab3, x3, y3);
    *reinterpret_cast<float4*>(g_AO + ((b * 1024 + qA) * 28 + h * 4)) =
        make_float4(x0 * iA, x1 * iA, x2 * iA, x3 * iA);
    *reinterpret_cast<float4*>(g_AO + ((b * 1024 + qA + 128) * 28 + h * 4)) =
        make_float4(y0 * iB, y1 * iB, y2 * iB, y3 * iB);
    up2(acd0, x0, y0); up2(acd1, x1, y1); up2(acd2, x2, y2); up2(acd3, x3, y3);
    *reinterpret_cast<float4*>(g_AO + ((b * 1024 + qA + 256) * 28 + h * 4)) =
        make_float4(x0 * iC, x1 * iC, x2 * iC, x3 * iC);
    *reinterpret_cast<float4*>(g_AO + ((b * 1024 + qA + 384) * 28 + h * 4)) =
        make_float4(y0 * iD, y1 * iD, y2 * iD, y3 * iD);
}

// ---------------------------------------------------------------------------
// K3: LayerNorm(28) + FFN(28->7) + ReLU + residual -> out7 (d_out head),
// then Q2/K2 projections (7->28) into scratch. 1 thread per row.
// ---------------------------------------------------------------------------
__global__ void k_lnffn(const float* __restrict__ x,
                        const float* __restrict__ lnw, const float* __restrict__ lnb,
                        const float* __restrict__ W1,  const float* __restrict__ b1,
                        const float* __restrict__ Wq2, const float* __restrict__ bq2,
                        const float* __restrict__ Wk2, const float* __restrict__ bk2,
                        float* __restrict__ out7) {
    __shared__ float s_lnw[28], s_lnb[28], s_W1[196], s_b1[7];
    __shared__ float s_Wq2[196], s_bq2[28], s_Wk2[196], s_bk2[28];
    int tid = threadIdx.x;
    for (int i = tid; i < 196; i += blockDim.x) { s_W1[i] = W1[i]; s_Wq2[i] = Wq2[i]; s_Wk2[i] = Wk2[i]; }
    if (tid < 28) { s_lnw[tid] = lnw[tid]; s_lnb[tid] = lnb[tid]; s_bq2[tid] = bq2[tid]; s_bk2[tid] = bk2[tid]; }
    if (tid < 7)  { s_b1[tid] = b1[tid]; }
    __syncthreads();

    int r = blockIdx.x * blockDim.x + tid;
    float a[28];
    const float4* ap = reinterpret_cast<const float4*>(g_AO + r * 28);
#pragma unroll
    for (int i = 0; i < 7; i++) {
        float4 t = ap[i];
        a[4*i] = t.x; a[4*i+1] = t.y; a[4*i+2] = t.z; a[4*i+3] = t.w;
    }
    float mu = 0.f;
#pragma unroll
    for (int j = 0; j < 28; j++) mu += a[j];
    mu *= (1.f / 28.f);
    float var = 0.f;
#pragma unroll
    for (int j = 0; j < 28; j++) { float d = a[j] - mu; var += d * d; }
    var *= (1.f / 28.f);
    float rs = rsqrtf(var + 1e-5f);

    float y[28];
#pragma unroll
    for (int j = 0; j < 28; j++) y[j] = (a[j] - mu) * rs * s_lnw[j] + s_lnb[j];

    float z[7];
#pragma unroll
    for (int i = 0; i < 7; i++) {
        float t = s_b1[i];
#pragma unroll
        for (int j = 0; j < 28; j++) t += y[j] * s_W1[j * 7 + i];
        t = fmaxf(t, 0.f) + x[r * 7 + i];
        z[i] = t;
        out7[r * 7 + i] = t;
    }
#pragma unroll
    for (int j = 0; j < 28; j++) {
        float tq = s_bq2[j], tk = s_bk2[j];
#pragma unroll
        for (int i = 0; i < 7; i++) {
            tq += z[i] * s_Wq2[i * 28 + j];
            tk += z[i] * s_Wk2[i * 28 + j];
        }
        g_Q2[r * 28 + j] = tq;
        g_K2[r * 28 + j] = tk;
    }
}

// ---------------------------------------------------------------------------
// K4: second attention weights. K2[b] (112KB) in dynamic SMEM; each warp-iter
// handles 4 q rows so every K2 row (7x LDS.128, reused as 14 u64) feeds 4
// packed-dot chains (f32x2 across d). Max-free softmax streams p to gmem,
// accumulates row sums, then L2-hit readback scales by 1/sum.
// 64-row tiles -> 256 blocks; 1 CTA/SM (smem+regs), 8 warps.
// ---------------------------------------------------------------------------
__global__ void __launch_bounds__(256, 1) k_attn2(float* __restrict__ out) {
    extern __shared__ float K2s[];                 // 1024*28 floats
    int b = blockIdx.y, tile = blockIdx.x;         // 16 tiles of 64 q rows
    {
        const float4* src = reinterpret_cast<const float4*>(g_K2 + b * SS * 28);
        float4* dst = reinterpret_cast<float4*>(K2s);
        for (int t = threadIdx.x; t < 1024 * 7; t += 256) dst[t] = src[t];
    }
    __syncthreads();

    int warp = threadIdx.x >> 5, lane = threadIdx.x & 31;
    const float SC2 = 1.4426950408889634f / 2.6457513110645906f; // log2(e)/sqrt(7)

#pragma unroll 1
    for (int rep = 0; rep < 2; rep++) {
        int q0 = tile * 64 + (rep * 8 + warp) * 4;

        u64 Qp[4][14];
#pragma unroll
        for (int r = 0; r < 4; r++) {
            const float4* qp = reinterpret_cast<const float4*>(g_Q2 + (b * 1024 + q0 + r) * 28);
#pragma unroll
            for (int i = 0; i < 7; i++) {
                float4 t = qp[i];
                Qp[r][2*i]   = pk2(t.x * SC2, t.y * SC2);
                Qp[r][2*i+1] = pk2(t.z * SC2, t.w * SC2);
            }
        }

        float* o0 = out + (b * 1024 + q0) * 1024;
        float su0 = 0.f, su1 = 0.f, su2 = 0.f, su3 = 0.f;
#pragma unroll 2
        for (int i = 0; i < 32; i++) {
            int k = i * 32 + lane;
            const ulonglong2* kr = reinterpret_cast<const ulonglong2*>(&K2s[k * 28]);
            ulonglong2 kk[7];
#pragma unroll
            for (int j = 0; j < 7; j++) kk[j] = kr[j];
            float p[4];
#pragma unroll
            for (int r = 0; r < 4; r++) {
                u64 acc = f2mul(Qp[r][0], kk[0].x);
                acc = f2fma(Qp[r][1],  kk[0].y, acc);
                acc = f2fma(Qp[r][2],  kk[1].x, acc);
                acc = f2fma(Qp[r][3],  kk[1].y, acc);
                acc = f2fma(Qp[r][4],  kk[2].x, acc);
                acc = f2fma(Qp[r][5],  kk[2].y, acc);
                acc = f2fma(Qp[r][6],  kk[3].x, acc);
                acc = f2fma(Qp[r][7],  kk[3].y, acc);
                acc = f2fma(Qp[r][8],  kk[4].x, acc);
                acc = f2fma(Qp[r][9],  kk[4].y, acc);
                acc = f2fma(Qp[r][10], kk[5].x, acc);
                acc = f2fma(Qp[r][11], kk[5].y, acc);
                acc = f2fma(Qp[r][12], kk[6].x, acc);
                acc = f2fma(Qp[r][13], kk[6].y, acc);
                float lo, hi; up2(acc, lo, hi);
                p[r] = ex2(lo + hi);
            }
            su0 += p[0]; su1 += p[1]; su2 += p[2]; su3 += p[3];
            o0[k]        = p[0];
            o0[1024 + k] = p[1];
            o0[2048 + k] = p[2];
            o0[3072 + k] = p[3];
        }
#pragma unroll
        for (int o = 16; o > 0; o >>= 1) {
            su0 += __shfl_xor_sync(0xffffffffu, su0, o);
            su1 += __shfl_xor_sync(0xffffffffu, su1, o);
            su2 += __shfl_xor_sync(0xffffffffu, su2, o);
            su3 += __shfl_xor_sync(0xffffffffu, su3, o);
        }
        float iv0 = 1.f / su0, iv1 = 1.f / su1, iv2 = 1.f / su2, iv3 = 1.f / su3;

        // readback (L2-resident) + normalize
#pragma unroll 4
        for (int i = 0; i < 32; i++) {
            int k = i * 32 + lane;
            o0[k]        *= iv0;
            o0[1024 + k] *= iv1;
            o0[2048 + k] *= iv2;
            o0[3072 + k] *= iv3;
        }
    }
}

// ---------------------------------------------------------------------------
extern "C" void kernel_launch(void* const* d_in, const int* in_sizes, int n_in,
                              void* d_out, int out_size) {
    const float* x    = (const float*)d_in[0];
    const float* Wq   = (const float*)d_in[1];
    const float* bq   = (const float*)d_in[2];
    const float* Wk   = (const float*)d_in[3];
    const float* bk   = (const float*)d_in[4];
    const float* Wv   = (const float*)d_in[5];
    const float* bv   = (const float*)d_in[6];
    const float* lnw  = (const float*)d_in[7];
    const float* lnb  = (const float*)d_in[8];
    const float* W1   = (const float*)d_in[9];
    const float* b1   = (const float*)d_in[10];
    const float* Wq2  = (const float*)d_in[11];
    const float* bq2  = (const float*)d_in[12];
    const float* Wk2  = (const float*)d_in[13];
    const float* bk2  = (const float*)d_in[14];
    float* out = (float*)d_out;

    cudaFuncSetAttribute(k_attn1, cudaFuncAttributeMaxDynamicSharedMemorySize, 65536);
    cudaFuncSetAttribute(k_attn2, cudaFuncAttributeMaxDynamicSharedMemorySize,
                         1024 * 28 * sizeof(float));

    k_qkv<<<128, 128>>>(x, Wq, bq, Wk, bk, Wv, bv);
    k_attn1<<<dim3(2, 7, 16), 128, 65536>>>();
    k_lnffn<<<128, 128>>>(x, lnw, lnb, W1, b1, Wq2, bq2, Wk2, bk2, out);
    k_attn2<<<dim3(16, 16), 256, 1024 * 28 * sizeof(float)>>>(out + BB * SS * NIN);
}

// round 5
// speedup vs baseline: 2.4000x; 1.1531x over previous
#include <cuda_runtime.h>
#include <math.h>

#define BB 16
#define SS 1024
#define NIN 7
#define NHID 28
#define HEADS 7
#define HD 4

// Scratch (device globals — no allocation allowed)
__device__ float g_Q [BB*HEADS*SS*HD];
__device__ float g_K [BB*HEADS*SS*HD];
__device__ float g_V [BB*HEADS*SS*HD];
__device__ float g_AO[BB*SS*NHID];
__device__ float g_Q2[BB*SS*NHID];
__device__ float g_K2[BB*SS*NHID];

// ---------------------------------------------------------------------------
// helpers
// ---------------------------------------------------------------------------
typedef unsigned long long u64;
__device__ __forceinline__ float ex2(float x) {            // single MUFU.EX2
    float r; asm("ex2.approx.ftz.f32 %0, %1;" : "=f"(r) : "f"(x)); return r;
}
__device__ __forceinline__ u64 pk2(float a, float b) {
    u64 r; asm("mov.b64 %0, {%1,%2};" : "=l"(r) : "f"(a), "f"(b)); return r;
}
__device__ __forceinline__ void up2(u64 v, float& a, float& b) {
    asm("mov.b64 {%0,%1}, %2;" : "=f"(a), "=f"(b) : "l"(v));
}
__device__ __forceinline__ u64 f2fma(u64 a, u64 b, u64 c) {
    u64 d; asm("fma.rn.f32x2 %0, %1, %2, %3;" : "=l"(d) : "l"(a), "l"(b), "l"(c)); return d;
}
__device__ __forceinline__ u64 f2mul(u64 a, u64 b) {
    u64 d; asm("mul.rn.f32x2 %0, %1, %2;" : "=l"(d) : "l"(a), "l"(b)); return d;
}
__device__ __forceinline__ u64 f2add(u64 a, u64 b) {
    u64 d; asm("add.rn.f32x2 %0, %1, %2;" : "=l"(d) : "l"(a), "l"(b)); return d;
}

// ---------------------------------------------------------------------------
// K1: QKV projection. 1 thread per (b,s) row. Q/K/V stored [B,H,S,4] (float4).
// ---------------------------------------------------------------------------
__global__ void k_qkv(const float* __restrict__ x,
                      const float* __restrict__ Wq, const float* __restrict__ bq,
                      const float* __restrict__ Wk, const float* __restrict__ bk,
                      const float* __restrict__ Wv, const float* __restrict__ bv) {
    __shared__ float sw[672];
    int tid = threadIdx.x;
    for (int i = tid; i < 196; i += blockDim.x) {
        sw[i] = Wq[i]; sw[224 + i] = Wk[i]; sw[448 + i] = Wv[i];
    }
    if (tid < 28) { sw[196 + tid] = bq[tid]; sw[420 + tid] = bk[tid]; sw[644 + tid] = bv[tid]; }
    __syncthreads();

    int r = blockIdx.x * blockDim.x + tid;        // 0..16383
    int b = r >> 10, s = r & 1023;

    float xv[7];
#pragma unroll
    for (int i = 0; i < 7; i++) xv[i] = x[r * 7 + i];

#pragma unroll
    for (int h = 0; h < 7; h++) {
        float qa[4], ka[4], va[4];
#pragma unroll
        for (int d = 0; d < 4; d++) {
            int j = h * 4 + d;
            float aq = sw[196 + j], ak = sw[420 + j], av = sw[644 + j];
#pragma unroll
            for (int i = 0; i < 7; i++) {
                float xi = xv[i];
                aq += xi * sw[i * 28 + j];
                ak += xi * sw[224 + i * 28 + j];
                av += xi * sw[448 + i * 28 + j];
            }
            qa[d] = aq; ka[d] = ak; va[d] = av;
        }
        int o = (b * 7 + h) * 1024 + s;
        reinterpret_cast<float4*>(g_Q)[o] = make_float4(qa[0], qa[1], qa[2], qa[3]);
        reinterpret_cast<float4*>(g_K)[o] = make_float4(ka[0], ka[1], ka[2], ka[3]);
        reinterpret_cast<float4*>(g_V)[o] = make_float4(va[0], va[1], va[2], va[3]);
    }
}

// ---------------------------------------------------------------------------
// K2: first attention. 2 q rows per thread packed f32x2; K/V duplicated (k,k)
// in smem so each broadcast LDS serves both rows. Max-free softmax, ex2.approx.
// 128 thr, grid (4,7,16)=448 -> 3.03 waves; smem 64KB -> 3 CTA/SM = 12 warps.
// ---------------------------------------------------------------------------
__global__ void __launch_bounds__(128) k_attn1() {
    extern __shared__ ulonglong2 s1[];           // [0,2048): Kdup, [2048,4096): Vdup
    ulonglong2* Ks = s1;
    ulonglong2* Vs = s1 + 2048;
    int b = blockIdx.z, h = blockIdx.y, chunk = blockIdx.x;   // chunk in [0,4)
    int bh = b * 7 + h;
    const float4* Kg = reinterpret_cast<const float4*>(g_K) + bh * 1024;
    const float4* Vg = reinterpret_cast<const float4*>(g_V) + bh * 1024;
    for (int t = threadIdx.x; t < 1024; t += 128) {
        float4 kk = Kg[t];
        Ks[2*t]   = make_ulonglong2(pk2(kk.x, kk.x), pk2(kk.y, kk.y));
        Ks[2*t+1] = make_ulonglong2(pk2(kk.z, kk.z), pk2(kk.w, kk.w));
        float4 vv = Vg[t];
        Vs[2*t]   = make_ulonglong2(pk2(vv.x, vv.x), pk2(vv.y, vv.y));
        Vs[2*t+1] = make_ulonglong2(pk2(vv.z, vv.z), pk2(vv.w, vv.w));
    }
    __syncthreads();

    int qA = chunk * 256 + threadIdx.x;          // rows qA, qA+128
    float4 qa = reinterpret_cast<const float4*>(g_Q)[bh * 1024 + qA];
    float4 qb = reinterpret_cast<const float4*>(g_Q)[bh * 1024 + qA + 128];
    const float c = 0.5f * 1.4426950408889634f;  // 1/sqrt(4) * log2(e)
    u64 qp0 = pk2(qa.x * c, qb.x * c);
    u64 qp1 = pk2(qa.y * c, qb.y * c);
    u64 qp2 = pk2(qa.z * c, qb.z * c);
    u64 qp3 = pk2(qa.w * c, qb.w * c);

    u64 acc0 = 0ull, acc1 = 0ull, acc2 = 0ull, acc3 = 0ull, l2 = 0ull;
#pragma unroll 4
    for (int k = 0; k < 1024; k++) {
        ulonglong2 k01 = Ks[2*k];
        ulonglong2 k23 = Ks[2*k+1];
        u64 s2 = f2mul(qp0, k01.x);
        s2 = f2fma(qp1, k01.y, s2);
        s2 = f2fma(qp2, k23.x, s2);
        s2 = f2fma(qp3, k23.y, s2);
        float sa, sb; up2(s2, sa, sb);
        u64 p2 = pk2(ex2(sa), ex2(sb));
        ulonglong2 v01 = Vs[2*k];
        ulonglong2 v23 = Vs[2*k+1];
        acc0 = f2fma(p2, v01.x, acc0);
        acc1 = f2fma(p2, v01.y, acc1);
        acc2 = f2fma(p2, v23.x, acc2);
        acc3 = f2fma(p2, v23.y, acc3);
        l2 = f2add(l2, p2);
    }
    float lA, lB; up2(l2, lA, lB);
    float iA = 1.f / lA, iB = 1.f / lB;
    float x0, y0, x1, y1, x2, y2, x3, y3;
    up2(acc0, x0, y0); up2(acc1, x1, y1); up2(acc2, x2, y2); up2(acc3, x3, y3);
    *reinterpret_cast<float4*>(g_AO + ((b * 1024 + qA) * 28 + h * 4)) =
        make_float4(x0 * iA, x1 * iA, x2 * iA, x3 * iA);
    *reinterpret_cast<float4*>(g_AO + ((b * 1024 + qA + 128) * 28 + h * 4)) =
        make_float4(y0 * iB, y1 * iB, y2 * iB, y3 * iB);
}

// ---------------------------------------------------------------------------
// K3: LayerNorm(28) + FFN(28->7) + ReLU + residual -> out7 (d_out head),
// then Q2/K2 projections (7->28) into scratch. 1 thread per row.
// ---------------------------------------------------------------------------
__global__ void k_lnffn(const float* __restrict__ x,
                        const float* __restrict__ lnw, const float* __restrict__ lnb,
                        const float* __restrict__ W1,  const float* __restrict__ b1,
                        const float* __restrict__ Wq2, const float* __restrict__ bq2,
                        const float* __restrict__ Wk2, const float* __restrict__ bk2,
                        float* __restrict__ out7) {
    __shared__ float s_lnw[28], s_lnb[28], s_W1[196], s_b1[7];
    __shared__ float s_Wq2[196], s_bq2[28], s_Wk2[196], s_bk2[28];
    int tid = threadIdx.x;
    for (int i = tid; i < 196; i += blockDim.x) { s_W1[i] = W1[i]; s_Wq2[i] = Wq2[i]; s_Wk2[i] = Wk2[i]; }
    if (tid < 28) { s_lnw[tid] = lnw[tid]; s_lnb[tid] = lnb[tid]; s_bq2[tid] = bq2[tid]; s_bk2[tid] = bk2[tid]; }
    if (tid < 7)  { s_b1[tid] = b1[tid]; }
    __syncthreads();

    int r = blockIdx.x * blockDim.x + tid;
    float a[28];
    const float4* ap = reinterpret_cast<const float4*>(g_AO + r * 28);
#pragma unroll
    for (int i = 0; i < 7; i++) {
        float4 t = ap[i];
        a[4*i] = t.x; a[4*i+1] = t.y; a[4*i+2] = t.z; a[4*i+3] = t.w;
    }
    float mu = 0.f;
#pragma unroll
    for (int j = 0; j < 28; j++) mu += a[j];
    mu *= (1.f / 28.f);
    float var = 0.f;
#pragma unroll
    for (int j = 0; j < 28; j++) { float d = a[j] - mu; var += d * d; }
    var *= (1.f / 28.f);
    float rs = rsqrtf(var + 1e-5f);

    float y[28];
#pragma unroll
    for (int j = 0; j < 28; j++) y[j] = (a[j] - mu) * rs * s_lnw[j] + s_lnb[j];

    float z[7];
#pragma unroll
    for (int i = 0; i < 7; i++) {
        float t = s_b1[i];
#pragma unroll
        for (int j = 0; j < 28; j++) t += y[j] * s_W1[j * 7 + i];
        t = fmaxf(t, 0.f) + x[r * 7 + i];
        z[i] = t;
        out7[r * 7 + i] = t;
    }
#pragma unroll
    for (int j = 0; j < 28; j++) {
        float tq = s_bq2[j], tk = s_bk2[j];
#pragma unroll
        for (int i = 0; i < 7; i++) {
            tq += z[i] * s_Wq2[i * 28 + j];
            tk += z[i] * s_Wk2[i * 28 + j];
        }
        g_Q2[r * 28 + j] = tq;
        g_K2[r * 28 + j] = tk;
    }
}

// ---------------------------------------------------------------------------
// K4: second attention weights. K2[b] (112KB) in dynamic SMEM; 4 q rows per
// warp-iter (f32x2 packed across d), K2-row loads software-pipelined via
// explicit ping-pong double buffer so LDS latency hides under the FMA block.
// Max-free softmax streams p to gmem + L2-hit readback normalize.
// ---------------------------------------------------------------------------
__global__ void __launch_bounds__(256, 1) k_attn2(float* __restrict__ out) {
    extern __shared__ float K2s[];                 // 1024*28 floats
    int b = blockIdx.y, tile = blockIdx.x;         // 16 tiles of 64 q rows
    {
        const float4* src = reinterpret_cast<const float4*>(g_K2 + b * SS * 28);
        float4* dst = reinterpret_cast<float4*>(K2s);
        for (int t = threadIdx.x; t < 1024 * 7; t += 256) dst[t] = src[t];
    }
    __syncthreads();

    int warp = threadIdx.x >> 5, lane = threadIdx.x & 31;
    const float SC2 = 1.4426950408889634f / 2.6457513110645906f; // log2(e)/sqrt(7)

#pragma unroll 1
    for (int rep = 0; rep < 2; rep++) {
        int q0 = tile * 64 + (rep * 8 + warp) * 4;

        u64 Qp[4][14];
#pragma unroll
        for (int r = 0; r < 4; r++) {
            const float4* qp = reinterpret_cast<const float4*>(g_Q2 + (b * 1024 + q0 + r) * 28);
#pragma unroll
            for (int i = 0; i < 7; i++) {
                float4 t = qp[i];
                Qp[r][2*i]   = pk2(t.x * SC2, t.y * SC2);
                Qp[r][2*i+1] = pk2(t.z * SC2, t.w * SC2);
            }
        }

        float* o0 = out + (b * 1024 + q0) * 1024;
        float su0 = 0.f, su1 = 0.f, su2 = 0.f, su3 = 0.f;

        ulonglong2 cur[7], nxt[7];
#pragma unroll
        for (int j = 0; j < 7; j++)
            cur[j] = reinterpret_cast<const ulonglong2*>(&K2s[lane * 28])[j];

#pragma unroll 2
        for (int i = 0; i < 32; i++) {
            // prefetch next K2 row (wraps to row 'lane' on last iter; harmless)
            int ni = ((i + 1) & 31) * 32 + lane;
            const ulonglong2* nr = reinterpret_cast<const ulonglong2*>(&K2s[ni * 28]);
#pragma unroll
            for (int j = 0; j < 7; j++) nxt[j] = nr[j];

            int k = i * 32 + lane;
            float p[4];
#pragma unroll
            for (int r = 0; r < 4; r++) {
                u64 acc = f2mul(Qp[r][0], cur[0].x);
                acc = f2fma(Qp[r][1],  cur[0].y, acc);
                acc = f2fma(Qp[r][2],  cur[1].x, acc);
                acc = f2fma(Qp[r][3],  cur[1].y, acc);
                acc = f2fma(Qp[r][4],  cur[2].x, acc);
                acc = f2fma(Qp[r][5],  cur[2].y, acc);
                acc = f2fma(Qp[r][6],  cur[3].x, acc);
                acc = f2fma(Qp[r][7],  cur[3].y, acc);
                acc = f2fma(Qp[r][8],  cur[4].x, acc);
                acc = f2fma(Qp[r][9],  cur[4].y, acc);
                acc = f2fma(Qp[r][10], cur[5].x, acc);
                acc = f2fma(Qp[r][11], cur[5].y, acc);
                acc = f2fma(Qp[r][12], cur[6].x, acc);
                acc = f2fma(Qp[r][13], cur[6].y, acc);
                float lo, hi; up2(acc, lo, hi);
                p[r] = ex2(lo + hi);
            }
            su0 += p[0]; su1 += p[1]; su2 += p[2]; su3 += p[3];
            o0[k]        = p[0];
            o0[1024 + k] = p[1];
            o0[2048 + k] = p[2];
            o0[3072 + k] = p[3];
#pragma unroll
            for (int j = 0; j < 7; j++) cur[j] = nxt[j];
        }
#pragma unroll
        for (int o = 16; o > 0; o >>= 1) {
            su0 += __shfl_xor_sync(0xffffffffu, su0, o);
            su1 += __shfl_xor_sync(0xffffffffu, su1, o);
            su2 += __shfl_xor_sync(0xffffffffu, su2, o);
            su3 += __shfl_xor_sync(0xffffffffu, su3, o);
        }
        float iv0 = 1.f / su0, iv1 = 1.f / su1, iv2 = 1.f / su2, iv3 = 1.f / su3;

        // readback (L2-resident) + normalize
#pragma unroll 4
        for (int i = 0; i < 32; i++) {
            int k = i * 32 + lane;
            o0[k]        *= iv0;
            o0[1024 + k] *= iv1;
            o0[2048 + k] *= iv2;
            o0[3072 + k] *= iv3;
        }
    }
}

// ---------------------------------------------------------------------------
extern "C" void kernel_launch(void* const* d_in, const int* in_sizes, int n_in,
                              void* d_out, int out_size) {
    const float* x    = (const float*)d_in[0];
    const float* Wq   = (const float*)d_in[1];
    const float* bq   = (const float*)d_in[2];
    const float* Wk   = (const float*)d_in[3];
    const float* bk   = (const float*)d_in[4];
    const float* Wv   = (const float*)d_in[5];
    const float* bv   = (const float*)d_in[6];
    const float* lnw  = (const float*)d_in[7];
    const float* lnb  = (const float*)d_in[8];
    const float* W1   = (const float*)d_in[9];
    const float* b1   = (const float*)d_in[10];
    const float* Wq2  = (const float*)d_in[11];
    const float* bq2  = (const float*)d_in[12];
    const float* Wk2  = (const float*)d_in[13];
    const float* bk2  = (const float*)d_in[14];
    float* out = (float*)d_out;

    cudaFuncSetAttribute(k_attn1, cudaFuncAttributeMaxDynamicSharedMemorySize, 65536);
    cudaFuncSetAttribute(k_attn2, cudaFuncAttributeMaxDynamicSharedMemorySize,
                         1024 * 28 * sizeof(float));

    k_qkv<<<128, 128>>>(x, Wq, bq, Wk, bk, Wv, bv);
    k_attn1<<<dim3(4, 7, 16), 128, 65536>>>();
    k_lnffn<<<128, 128>>>(x, lnw, lnb, W1, b1, Wq2, bq2, Wk2, bk2, out);
    k_attn2<<<dim3(16, 16), 256, 1024 * 28 * sizeof(float)>>>(out + BB * SS * NIN);
}